// round 3
// baseline (speedup 1.0000x reference)
#include <cuda_runtime.h>

#define NNODES 100000
#define NEDGES 1600000
#define F0 128
#define F1 64
#define F2 16
#define NB1 ((NNODES + 255) / 256)   // 391 scan blocks

typedef unsigned long long ull;

// Scratch (device globals: allocation-free, graph-safe)
__device__ float g_deg [NNODES];
__device__ float g_dinv[NNODES];
__device__ float g_h1  [NNODES * F1];
__device__ float g_agg1[NNODES * F1];
__device__ float g_h2  [NNODES * F2];
__device__ float g_agg2[NNODES * F2];
// edge sort scratch
__device__ int   g_hist  [NNODES];
__device__ int   g_off   [NNODES];
__device__ int   g_cursor[NNODES];
__device__ int   g_bsum  [512];
__device__ int   g_ssrc  [NEDGES];
__device__ int   g_sdst  [NEDGES];

// ---------------------------------------------------------------------------
// f32x2 packed helpers (sm_103a FFMA2 — only reachable via PTX)
// ---------------------------------------------------------------------------
__device__ __forceinline__ ull pack2(float lo, float hi) {
    ull r; asm("mov.b64 %0, {%1, %2};" : "=l"(r) : "f"(lo), "f"(hi)); return r;
}
__device__ __forceinline__ void unpack2(ull v, float& lo, float& hi) {
    asm("mov.b64 {%0, %1}, %2;" : "=f"(lo), "=f"(hi) : "l"(v));
}
__device__ __forceinline__ void fma2(ull& acc, ull a, ull b) {
    asm("fma.rn.f32x2 %0, %1, %2, %0;" : "+l"(acc) : "l"(a), "l"(b));
}
__device__ __forceinline__ ull mul2(ull a, ull b) {
    ull r; asm("mul.rn.f32x2 %0, %1, %2;" : "=l"(r) : "l"(a), "l"(b)); return r;
}

// ---------------------------------------------------------------------------
// Init: zero aggregation buffers + hist, deg = 1 (self loop)
// ---------------------------------------------------------------------------
__global__ void gcn_init_kernel() {
    int i = blockIdx.x * blockDim.x + threadIdx.x;
    if (i < NNODES * F1) g_agg1[i] = 0.f;
    if (i < NNODES * F2) g_agg2[i] = 0.f;
    if (i < NNODES)    { g_deg[i] = 1.f; g_hist[i] = 0; }
}

// ---------------------------------------------------------------------------
// Degree (dst) + out-degree histogram (src) in one pass
// ---------------------------------------------------------------------------
__global__ void gcn_deg_hist_kernel(const int* __restrict__ src,
                                    const int* __restrict__ dst) {
    int e = blockIdx.x * blockDim.x + threadIdx.x;
    if (e < NEDGES) {
        atomicAdd(&g_deg[dst[e]], 1.0f);
        atomicAdd(&g_hist[src[e]], 1);
    }
}

// ---------------------------------------------------------------------------
// Two-level exclusive scan of g_hist -> per-node cursors
// ---------------------------------------------------------------------------
__global__ void gcn_scan1_kernel() {   // 391 blocks x 256
    __shared__ int s[256];
    int tid = threadIdx.x;
    int i = blockIdx.x * 256 + tid;
    int v = (i < NNODES) ? g_hist[i] : 0;
    s[tid] = v;
    __syncthreads();
#pragma unroll
    for (int o = 1; o < 256; o <<= 1) {
        int t = (tid >= o) ? s[tid - o] : 0;
        __syncthreads();
        s[tid] += t;
        __syncthreads();
    }
    if (i < NNODES) g_off[i] = s[tid] - v;       // exclusive within block
    if (tid == 255) g_bsum[blockIdx.x] = s[255]; // block total
}

__global__ void gcn_scan2_kernel() {   // 1 block x 512, scans NB1 totals
    __shared__ int s[512];
    int tid = threadIdx.x;
    int v = (tid < NB1) ? g_bsum[tid] : 0;
    s[tid] = v;
    __syncthreads();
#pragma unroll
    for (int o = 1; o < 512; o <<= 1) {
        int t = (tid >= o) ? s[tid - o] : 0;
        __syncthreads();
        s[tid] += t;
        __syncthreads();
    }
    if (tid < NB1) g_bsum[tid] = s[tid] - v;     // exclusive block offsets
}

// dinv = rsqrt(deg); cursor = global exclusive prefix of out-degree
__global__ void gcn_dinv_cursor_kernel() {
    int i = blockIdx.x * blockDim.x + threadIdx.x;
    if (i < NNODES) {
        g_dinv[i] = rsqrtf(g_deg[i]);
        g_cursor[i] = g_off[i] + g_bsum[i >> 8];
    }
}

// Permute edges into src-sorted order
__global__ void gcn_permute_kernel(const int* __restrict__ src,
                                   const int* __restrict__ dst) {
    int e = blockIdx.x * blockDim.x + threadIdx.x;
    if (e < NEDGES) {
        int s = src[e], d = dst[e];
        int p = atomicAdd(&g_cursor[s], 1);
        g_ssrc[p] = s;
        g_sdst[p] = d;
    }
}

// ---------------------------------------------------------------------------
// GEMM1: h1[v,:] = (x[v,:] @ W1) * dinv[v]     [N,128]x[128,64]
// Column-pair FFMA2, zero packing movs:
//   - W pairs come packed from LDS.128 (aligned register pairs)
//   - x broadcast pairs pre-duplicated in smem: xs_dup[r][k] = (x, x)
// Block: 256 threads, BM=64 rows; thread tile 4 rows x 4 cols.
// ---------------------------------------------------------------------------
#define BM 64
extern __shared__ float s_gemm1[];   // Ws[F0*F1] (32KB) then xs_dup[BM*F0] float2 (64KB)

__global__ void __launch_bounds__(256, 2) gcn_gemm1_kernel(
        const float* __restrict__ x, const float* __restrict__ W1) {
    float*  Ws = s_gemm1;                              // 32 KB
    float2* xd = (float2*)(s_gemm1 + F0 * F1);         // 64 KB, 8B-aligned
    int tid = threadIdx.x;
    int row0 = blockIdx.x * BM;

    // Stage W1 (8192 floats), coalesced float4
    for (int i = tid; i < F0 * F1 / 4; i += 256)
        *(float4*)&Ws[i * 4] = *(const float4*)&W1[i * 4];

    // Stage x tile duplicated: xd[r*F0 + k] = (x[v,k], x[v,k])
    for (int i = tid; i < BM * 32; i += 256) {
        int r = i >> 5, kq = i & 31;
        int v = row0 + r;
        float4 xv = (v < NNODES) ? *(const float4*)&x[v * F0 + kq * 4]
                                 : make_float4(0.f, 0.f, 0.f, 0.f);
        float2* p = &xd[r * F0 + kq * 4];
        p[0] = make_float2(xv.x, xv.x);
        p[1] = make_float2(xv.y, xv.y);
        p[2] = make_float2(xv.z, xv.z);
        p[3] = make_float2(xv.w, xv.w);
    }
    __syncthreads();

    int ty = tid >> 4;          // 0..15 -> rows 4*ty .. 4*ty+3
    int tx = tid & 15;          // 0..15 -> cols 4*tx .. 4*tx+3 (2 col-pairs)
    const float2* xrow = &xd[(ty * 4) * F0];

    ull acc[4][2];
#pragma unroll
    for (int r = 0; r < 4; r++) { acc[r][0] = 0ull; acc[r][1] = 0ull; }

#pragma unroll 4
    for (int k = 0; k < F0; k++) {
        ulonglong2 w = *(const ulonglong2*)&Ws[k * F1 + tx * 4]; // (w0,w1),(w2,w3)
#pragma unroll
        for (int r = 0; r < 4; r++) {
            ull px = *(const ull*)&xrow[r * F0 + k];             // (x, x)
            fma2(acc[r][0], px, w.x);
            fma2(acc[r][1], px, w.y);
        }
    }

    // Epilogue: scale by dinv, store float4 per row
#pragma unroll
    for (int r = 0; r < 4; r++) {
        int v = row0 + ty * 4 + r;
        if (v >= NNODES) break;
        float dv = g_dinv[v];
        ull dd = pack2(dv, dv);
        float o0, o1, o2, o3;
        unpack2(mul2(acc[r][0], dd), o0, o1);
        unpack2(mul2(acc[r][1], dd), o2, o3);
        *(float4*)&g_h1[v * F1 + tx * 4] = make_float4(o0, o1, o2, o3);
    }
}

// ---------------------------------------------------------------------------
// Edge scatter layer 1 over src-sorted edges: agg1[dst] += h1[src]
// (gathers of h1 rows hit L1 due to src locality)
// ---------------------------------------------------------------------------
__global__ void gcn_scatter1_kernel() {
    int t = blockIdx.x * blockDim.x + threadIdx.x;
    int e = t >> 4;
    int lane = t & 15;
    if (e >= NEDGES) return;
    int s = g_ssrc[e], d = g_sdst[e];
    float4 v = *(const float4*)&g_h1[s * F1 + lane * 4];
    float* p = &g_agg1[d * F1 + lane * 4];
    asm volatile("red.global.add.v4.f32 [%0], {%1, %2, %3, %4};"
                 :: "l"(p), "f"(v.x), "f"(v.y), "f"(v.z), "f"(v.w) : "memory");
}

// ---------------------------------------------------------------------------
// Fused layer-2 input: t = leaky_relu(dinv*(agg1+h1) + b1); h2 = (t@W2)*dinv
// ---------------------------------------------------------------------------
__global__ void gcn_layer2_kernel(const float* __restrict__ W2,
                                  const float* __restrict__ b1) {
    __shared__ __align__(16) float W2s[F1 * F2];
    __shared__ __align__(16) float ts[16][F1];
    __shared__ float b1s[F1];
    int tid = threadIdx.x;
    for (int i = tid; i < F1 * F2; i += 256) W2s[i] = W2[i];
    if (tid < F1) b1s[tid] = b1[tid];
    __syncthreads();

    int r = tid >> 4;
    int m = tid & 15;
    int v = blockIdx.x * 16 + r;
    float dv = g_dinv[v];

    {
        int j = m * 4;
        float4 a = *(const float4*)&g_agg1[v * F1 + j];
        float4 h = *(const float4*)&g_h1 [v * F1 + j];
        float4 t;
        t.x = dv * (a.x + h.x) + b1s[j + 0];
        t.y = dv * (a.y + h.y) + b1s[j + 1];
        t.z = dv * (a.z + h.z) + b1s[j + 2];
        t.w = dv * (a.w + h.w) + b1s[j + 3];
        t.x = t.x >= 0.f ? t.x : 0.2f * t.x;
        t.y = t.y >= 0.f ? t.y : 0.2f * t.y;
        t.z = t.z >= 0.f ? t.z : 0.2f * t.z;
        t.w = t.w >= 0.f ? t.w : 0.2f * t.w;
        *(float4*)&ts[r][j] = t;
    }
    __syncthreads();

    float acc = 0.f;
#pragma unroll
    for (int j = 0; j < F1; j++) acc += ts[r][j] * W2s[j * F2 + m];
    g_h2[v * F2 + m] = acc * dv;
}

// ---------------------------------------------------------------------------
// Edge scatter layer 2 over src-sorted edges: agg2[dst] += h2[src]
// ---------------------------------------------------------------------------
__global__ void gcn_scatter2_kernel() {
    int t = blockIdx.x * blockDim.x + threadIdx.x;
    int e = t >> 2;
    int lane = t & 3;
    if (e >= NEDGES) return;
    int s = g_ssrc[e], d = g_sdst[e];
    float4 v = *(const float4*)&g_h2[s * F2 + lane * 4];
    float* p = &g_agg2[d * F2 + lane * 4];
    asm volatile("red.global.add.v4.f32 [%0], {%1, %2, %3, %4};"
                 :: "l"(p), "f"(v.x), "f"(v.y), "f"(v.z), "f"(v.w) : "memory");
}

// ---------------------------------------------------------------------------
// Final: out = log_softmax(dinv*(agg2+h2) + b2)
// ---------------------------------------------------------------------------
__global__ void gcn_final_kernel(const float* __restrict__ b2,
                                 float* __restrict__ out) {
    int v = blockIdx.x * blockDim.x + threadIdx.x;
    if (v >= NNODES) return;
    float dv = g_dinv[v];
    float t[F2];
#pragma unroll
    for (int i = 0; i < 4; i++) {
        float4 a = *(const float4*)&g_agg2[v * F2 + i * 4];
        float4 h = *(const float4*)&g_h2 [v * F2 + i * 4];
        t[i * 4 + 0] = dv * (a.x + h.x) + b2[i * 4 + 0];
        t[i * 4 + 1] = dv * (a.y + h.y) + b2[i * 4 + 1];
        t[i * 4 + 2] = dv * (a.z + h.z) + b2[i * 4 + 2];
        t[i * 4 + 3] = dv * (a.w + h.w) + b2[i * 4 + 3];
    }
    float mx = t[0];
#pragma unroll
    for (int i = 1; i < F2; i++) mx = fmaxf(mx, t[i]);
    float s = 0.f;
#pragma unroll
    for (int i = 0; i < F2; i++) s += expf(t[i] - mx);
    float lse = mx + logf(s);
#pragma unroll
    for (int i = 0; i < 4; i++) {
        float4 o;
        o.x = t[i * 4 + 0] - lse;
        o.y = t[i * 4 + 1] - lse;
        o.z = t[i * 4 + 2] - lse;
        o.w = t[i * 4 + 3] - lse;
        *(float4*)&out[v * F2 + i * 4] = o;
    }
}

// ---------------------------------------------------------------------------
// Launch
// ---------------------------------------------------------------------------
extern "C" void kernel_launch(void* const* d_in, const int* in_sizes, int n_in,
                              void* d_out, int out_size) {
    const float* x  = (const float*)d_in[0];
    const int*   ei = (const int*)  d_in[1];
    const float* W1 = (const float*)d_in[2];
    const float* b1 = (const float*)d_in[3];
    const float* W2 = (const float*)d_in[4];
    const float* b2 = (const float*)d_in[5];
    float* out = (float*)d_out;

    const int* src = ei;
    const int* dst = ei + NEDGES;

    const int gemm1_smem = (F0 * F1 + BM * F0 * 2) * (int)sizeof(float); // 96 KB
    cudaFuncSetAttribute(gcn_gemm1_kernel,
                         cudaFuncAttributeMaxDynamicSharedMemorySize, gemm1_smem);

    gcn_init_kernel       <<<(NNODES * F1 + 255) / 256, 256>>>();
    gcn_deg_hist_kernel   <<<(NEDGES + 255) / 256, 256>>>(src, dst);
    gcn_scan1_kernel      <<<NB1, 256>>>();
    gcn_scan2_kernel      <<<1, 512>>>();
    gcn_dinv_cursor_kernel<<<(NNODES + 255) / 256, 256>>>();
    gcn_permute_kernel    <<<(NEDGES + 255) / 256, 256>>>(src, dst);
    gcn_gemm1_kernel      <<<(NNODES + BM - 1) / BM, 256, gemm1_smem>>>(x, W1);
    gcn_scatter1_kernel   <<<(NEDGES * 16) / 256, 256>>>();
    gcn_layer2_kernel     <<<NNODES / 16, 256>>>(W2, b1);
    gcn_scatter2_kernel   <<<(NEDGES * 4) / 256, 256>>>();
    gcn_final_kernel      <<<(NNODES + 255) / 256, 256>>>(b2, out);
}

// round 4
// speedup vs baseline: 1.3820x; 1.3820x over previous
#include <cuda_runtime.h>

#define NNODES 100000
#define NEDGES 1600000
#define F0 128
#define F1 64
#define F2 16
#define NB1 ((NNODES + 255) / 256)   // 391 scan blocks

typedef unsigned long long ull;

// Scratch (device globals: allocation-free, graph-safe)
__device__ float g_dinv[NNODES];
__device__ float g_h1  [NNODES * F1];   // h~ = (x@W1)*dinv[row]
__device__ float g_t   [NNODES * F1];   // activated layer-1 output
__device__ float g_h2  [NNODES * F2];   // h~2 = (t@W2)*dinv[row]
// dst-CSR scratch
__device__ int   g_hist  [NNODES];      // in-degree (dst)
__device__ int   g_off   [NNODES];
__device__ int   g_rowptr[NNODES];
__device__ int   g_cursor[NNODES];
__device__ int   g_bsum  [512];
__device__ int   g_csr   [NEDGES];      // src ids grouped by dst

// ---------------------------------------------------------------------------
// f32x2 packed helpers (sm_103a FFMA2 — only reachable via PTX)
// ---------------------------------------------------------------------------
__device__ __forceinline__ ull pack2(float lo, float hi) {
    ull r; asm("mov.b64 %0, {%1, %2};" : "=l"(r) : "f"(lo), "f"(hi)); return r;
}
__device__ __forceinline__ void unpack2(ull v, float& lo, float& hi) {
    asm("mov.b64 {%0, %1}, %2;" : "=f"(lo), "=f"(hi) : "l"(v));
}
__device__ __forceinline__ void fma2(ull& acc, ull a, ull b) {
    asm("fma.rn.f32x2 %0, %1, %2, %0;" : "+l"(acc) : "l"(a), "l"(b));
}
__device__ __forceinline__ ull mul2(ull a, ull b) {
    ull r; asm("mul.rn.f32x2 %0, %1, %2;" : "=l"(r) : "l"(a), "l"(b)); return r;
}

// ---------------------------------------------------------------------------
// 1. Init: zero dst histogram
// ---------------------------------------------------------------------------
__global__ void gcn_init_kernel() {
    int i = blockIdx.x * blockDim.x + threadIdx.x;
    if (i < NNODES) g_hist[i] = 0;
}

// ---------------------------------------------------------------------------
// 2. In-degree histogram over dst (also serves as degree: deg = 1 + hist)
// ---------------------------------------------------------------------------
__global__ void gcn_hist_kernel(const int* __restrict__ dst) {
    int e = blockIdx.x * blockDim.x + threadIdx.x;
    if (e < NEDGES) atomicAdd(&g_hist[dst[e]], 1);
}

// ---------------------------------------------------------------------------
// 3. dinv = rsqrt(1 + indeg)
// ---------------------------------------------------------------------------
__global__ void gcn_dinv_kernel() {
    int i = blockIdx.x * blockDim.x + threadIdx.x;
    if (i < NNODES) g_dinv[i] = rsqrtf(1.0f + (float)g_hist[i]);
}

// ---------------------------------------------------------------------------
// 4. GEMM1: h1[v,:] = (x[v,:] @ W1) * dinv[v]     [N,128]x[128,64]
// Column-pair FFMA2, zero packing movs (W pairs from LDS.128, x pairs
// pre-duplicated in smem). 256 thr, BM=64 rows, 4x4 thread tile.
// ---------------------------------------------------------------------------
#define BM 64
extern __shared__ float s_gemm1[];   // Ws[F0*F1] (32KB) then xs_dup (64KB)

__global__ void __launch_bounds__(256, 2) gcn_gemm1_kernel(
        const float* __restrict__ x, const float* __restrict__ W1) {
    float*  Ws = s_gemm1;
    float2* xd = (float2*)(s_gemm1 + F0 * F1);
    int tid = threadIdx.x;
    int row0 = blockIdx.x * BM;

    for (int i = tid; i < F0 * F1 / 4; i += 256)
        *(float4*)&Ws[i * 4] = *(const float4*)&W1[i * 4];

    for (int i = tid; i < BM * 32; i += 256) {
        int r = i >> 5, kq = i & 31;
        int v = row0 + r;
        float4 xv = (v < NNODES) ? *(const float4*)&x[v * F0 + kq * 4]
                                 : make_float4(0.f, 0.f, 0.f, 0.f);
        float2* p = &xd[r * F0 + kq * 4];
        p[0] = make_float2(xv.x, xv.x);
        p[1] = make_float2(xv.y, xv.y);
        p[2] = make_float2(xv.z, xv.z);
        p[3] = make_float2(xv.w, xv.w);
    }
    __syncthreads();

    int ty = tid >> 4;
    int tx = tid & 15;
    const float2* xrow = &xd[(ty * 4) * F0];

    ull acc[4][2];
#pragma unroll
    for (int r = 0; r < 4; r++) { acc[r][0] = 0ull; acc[r][1] = 0ull; }

#pragma unroll 4
    for (int k = 0; k < F0; k++) {
        ulonglong2 w = *(const ulonglong2*)&Ws[k * F1 + tx * 4];
#pragma unroll
        for (int r = 0; r < 4; r++) {
            ull px = *(const ull*)&xrow[r * F0 + k];
            fma2(acc[r][0], px, w.x);
            fma2(acc[r][1], px, w.y);
        }
    }

#pragma unroll
    for (int r = 0; r < 4; r++) {
        int v = row0 + ty * 4 + r;
        if (v >= NNODES) break;
        float dv = g_dinv[v];
        ull dd = pack2(dv, dv);
        float o0, o1, o2, o3;
        unpack2(mul2(acc[r][0], dd), o0, o1);
        unpack2(mul2(acc[r][1], dd), o2, o3);
        *(float4*)&g_h1[v * F1 + tx * 4] = make_float4(o0, o1, o2, o3);
    }
}

// ---------------------------------------------------------------------------
// 5-7. Two-level exclusive scan of g_hist -> rowptr + cursor
// ---------------------------------------------------------------------------
__global__ void gcn_scan1_kernel() {
    __shared__ int s[256];
    int tid = threadIdx.x;
    int i = blockIdx.x * 256 + tid;
    int v = (i < NNODES) ? g_hist[i] : 0;
    s[tid] = v;
    __syncthreads();
#pragma unroll
    for (int o = 1; o < 256; o <<= 1) {
        int t = (tid >= o) ? s[tid - o] : 0;
        __syncthreads();
        s[tid] += t;
        __syncthreads();
    }
    if (i < NNODES) g_off[i] = s[tid] - v;
    if (tid == 255) g_bsum[blockIdx.x] = s[255];
}

__global__ void gcn_scan2_kernel() {
    __shared__ int s[512];
    int tid = threadIdx.x;
    int v = (tid < NB1) ? g_bsum[tid] : 0;
    s[tid] = v;
    __syncthreads();
#pragma unroll
    for (int o = 1; o < 512; o <<= 1) {
        int t = (tid >= o) ? s[tid - o] : 0;
        __syncthreads();
        s[tid] += t;
        __syncthreads();
    }
    if (tid < NB1) g_bsum[tid] = s[tid] - v;
}

__global__ void gcn_rowptr_kernel() {
    int i = blockIdx.x * blockDim.x + threadIdx.x;
    if (i < NNODES) {
        int p = g_off[i] + g_bsum[i >> 8];
        g_rowptr[i] = p;
        g_cursor[i] = p;
    }
}

// ---------------------------------------------------------------------------
// 8. Permute: group src ids by dst (CSR fill)
// ---------------------------------------------------------------------------
__global__ void gcn_permute_kernel(const int* __restrict__ src,
                                   const int* __restrict__ dst) {
    int e = blockIdx.x * blockDim.x + threadIdx.x;
    if (e < NEDGES) {
        int d = dst[e];
        int p = atomicAdd(&g_cursor[d], 1);
        g_csr[p] = src[e];
    }
}

// ---------------------------------------------------------------------------
// 9. Layer-1 aggregation + activation (warp per node, float2 per lane):
//    t[v] = leaky_relu(dinv[v] * (h1[v] + sum_{s->v} h1[s]) + b1)
// ---------------------------------------------------------------------------
__global__ void gcn_agg1_kernel(const float* __restrict__ b1) {
    int w = (blockIdx.x * blockDim.x + threadIdx.x) >> 5;
    int lane = threadIdx.x & 31;
    if (w >= NNODES) return;
    int v = w;
    int beg = g_rowptr[v];
    int len = g_hist[v];

    float2 acc = *(const float2*)&g_h1[v * F1 + lane * 2];   // self loop

    const int* __restrict__ idx = &g_csr[beg];
    int i = 0;
    for (; i + 4 <= len; i += 4) {
        int s0 = idx[i], s1 = idx[i + 1], s2 = idx[i + 2], s3 = idx[i + 3];
        float2 u0 = *(const float2*)&g_h1[s0 * F1 + lane * 2];
        float2 u1 = *(const float2*)&g_h1[s1 * F1 + lane * 2];
        float2 u2 = *(const float2*)&g_h1[s2 * F1 + lane * 2];
        float2 u3 = *(const float2*)&g_h1[s3 * F1 + lane * 2];
        acc.x += u0.x + u1.x + u2.x + u3.x;
        acc.y += u0.y + u1.y + u2.y + u3.y;
    }
    for (; i < len; i++) {
        int s = idx[i];
        float2 u = *(const float2*)&g_h1[s * F1 + lane * 2];
        acc.x += u.x; acc.y += u.y;
    }

    float dv = g_dinv[v];
    float t0 = dv * acc.x + b1[lane * 2];
    float t1 = dv * acc.y + b1[lane * 2 + 1];
    t0 = t0 >= 0.f ? t0 : 0.2f * t0;
    t1 = t1 >= 0.f ? t1 : 0.2f * t1;
    *(float2*)&g_t[v * F1 + lane * 2] = make_float2(t0, t1);
}

// ---------------------------------------------------------------------------
// 10. GEMM2: h2[v,:] = (t[v,:] @ W2) * dinv[v]    [N,64]x[64,16]
// ---------------------------------------------------------------------------
__global__ void gcn_gemm2_kernel(const float* __restrict__ W2) {
    __shared__ __align__(16) float W2s[F1 * F2];
    __shared__ __align__(16) float ts[16][F1];
    int tid = threadIdx.x;
    for (int i = tid; i < F1 * F2; i += 256) W2s[i] = W2[i];

    int v0 = blockIdx.x * 16;
    for (int i = tid; i < 16 * 16; i += 256) {
        int r = i >> 4, q = i & 15;
        *(float4*)&ts[r][q * 4] = *(const float4*)&g_t[(v0 + r) * F1 + q * 4];
    }
    __syncthreads();

    int r = tid >> 4;
    int m = tid & 15;
    int v = v0 + r;
    float acc = 0.f;
#pragma unroll
    for (int j = 0; j < F1; j++) acc += ts[r][j] * W2s[j * F2 + m];
    g_h2[v * F2 + m] = acc * g_dinv[v];
}

// ---------------------------------------------------------------------------
// 11. Layer-2 aggregation + log_softmax (warp per node; lanes 0-15 handle
//     even edges, 16-31 odd edges, one feature per lane)
// ---------------------------------------------------------------------------
__global__ void gcn_agg2_kernel(const float* __restrict__ b2,
                                float* __restrict__ out) {
    int w = (blockIdx.x * blockDim.x + threadIdx.x) >> 5;
    int lane = threadIdx.x & 31;
    if (w >= NNODES) return;
    int v = w;
    int beg = g_rowptr[v];
    int len = g_hist[v];
    int f = lane & 15;

    float acc = 0.f;
    const int* __restrict__ idx = &g_csr[beg];
    // lanes 0-15 process even edges, lanes 16-31 odd edges
    for (int i = (lane >> 4); i < len; i += 2) {
        int s = idx[i];
        acc += g_h2[s * F2 + f];
    }
    // fold odd-half into even-half
    acc += __shfl_down_sync(0xffffffffu, acc, 16);

    // lanes 0-15 now hold the full neighbor sum for feature f
    float dv = g_dinv[v];
    float t = dv * (acc + g_h2[v * F2 + f]) + b2[f];

    // log_softmax across the 16 features (xor shuffles stay in the half-warp)
    float mx = t;
#pragma unroll
    for (int o = 8; o >= 1; o >>= 1)
        mx = fmaxf(mx, __shfl_xor_sync(0xffffffffu, mx, o));
    float ex = expf(t - mx);
    float sum = ex;
#pragma unroll
    for (int o = 8; o >= 1; o >>= 1)
        sum += __shfl_xor_sync(0xffffffffu, sum, o);
    float lse = mx + logf(sum);

    if (lane < 16) out[v * F2 + f] = t - lse;
}

// ---------------------------------------------------------------------------
// Launch
// ---------------------------------------------------------------------------
extern "C" void kernel_launch(void* const* d_in, const int* in_sizes, int n_in,
                              void* d_out, int out_size) {
    const float* x  = (const float*)d_in[0];
    const int*   ei = (const int*)  d_in[1];
    const float* W1 = (const float*)d_in[2];
    const float* b1 = (const float*)d_in[3];
    const float* W2 = (const float*)d_in[4];
    const float* b2 = (const float*)d_in[5];
    float* out = (float*)d_out;

    const int* src = ei;
    const int* dst = ei + NEDGES;

    const int gemm1_smem = (F0 * F1 + BM * F0 * 2) * (int)sizeof(float); // 96 KB
    cudaFuncSetAttribute(gcn_gemm1_kernel,
                         cudaFuncAttributeMaxDynamicSharedMemorySize, gemm1_smem);

    gcn_init_kernel   <<<(NNODES + 255) / 256, 256>>>();
    gcn_hist_kernel   <<<(NEDGES + 255) / 256, 256>>>(dst);
    gcn_dinv_kernel   <<<(NNODES + 255) / 256, 256>>>();
    gcn_gemm1_kernel  <<<(NNODES + BM - 1) / BM, 256, gemm1_smem>>>(x, W1);
    gcn_scan1_kernel  <<<NB1, 256>>>();
    gcn_scan2_kernel  <<<1, 512>>>();
    gcn_rowptr_kernel <<<(NNODES + 255) / 256, 256>>>();
    gcn_permute_kernel<<<(NEDGES + 255) / 256, 256>>>(src, dst);
    gcn_agg1_kernel   <<<(NNODES * 32 + 255) / 256, 256>>>(b1);
    gcn_gemm2_kernel  <<<NNODES / 16, 256>>>(W2);
    gcn_agg2_kernel   <<<(NNODES * 32 + 255) / 256, 256>>>(b2, out);
}